// round 1
// baseline (speedup 1.0000x reference)
#include <cuda_runtime.h>

#define NNODES 10000
#define NEDGES 160000
#define CINCH  32
#define H      64
#define T      12
#define OUTC   12
#define KW     3
#define FEAT   (H * T)  // 768

// ---------------- device scratch (no allocations allowed) ----------------
__device__ float g_bufA[NNODES * FEAT];
__device__ float g_bufB[NNODES * FEAT];
__device__ float g_bufC[NNODES * FEAT];
__device__ float g_dis[NNODES];                 // deg accumulator, then rsqrt(deg)
__device__ float g_wt1a[2 * H * CINCH * KW];    // transposed [c][k][o]
__device__ float g_wt1b[2 * H * H * KW];
__device__ float g_wt2a[2 * H * H * KW];
__device__ float g_wt2b[2 * H * H * KW];
__device__ float g_gc1T[H * H];                 // [c][o]
__device__ float g_gc2T[H * H];

// ---------------- weight transposes ----------------
// w[o][c][k]  ->  wT[(c*K+k)*128 + o]
__global__ void k_tw(const float* __restrict__ w, float* __restrict__ wT, int cin) {
    int idx = blockIdx.x * blockDim.x + threadIdx.x;
    int tot = 2 * H * cin * KW;
    if (idx >= tot) return;
    int o = idx / (cin * KW);
    int r = idx - o * cin * KW;
    int c = r / KW;
    int k = r - c * KW;
    wT[(c * KW + k) * (2 * H) + o] = w[idx];
}

// w[o][c] -> wT[c][o]
__global__ void k_gw(const float* __restrict__ w, float* __restrict__ wT) {
    int idx = blockIdx.x * blockDim.x + threadIdx.x;
    if (idx >= H * H) return;
    int o = idx / H, c = idx - o * H;
    wT[c * H + o] = w[idx];
}

// ---------------- degree / normalization ----------------
__global__ void k_deg_init() {
    int n = blockIdx.x * blockDim.x + threadIdx.x;
    if (n < NNODES) g_dis[n] = 1.0f;  // self-loop weight
}
__global__ void k_deg_acc(const int* __restrict__ dst, const float* __restrict__ ew) {
    int e = blockIdx.x * blockDim.x + threadIdx.x;
    if (e < NEDGES) atomicAdd(&g_dis[dst[e]], ew[e]);
}
__global__ void k_deg_fin() {
    int n = blockIdx.x * blockDim.x + threadIdx.x;
    if (n < NNODES) g_dis[n] = rsqrtf(g_dis[n]);  // deg >= 1 always
}

// ---------------- gated temporal conv ----------------
// block: 256 threads = 4 nodes x 64 output channels, each thread does all 12 t.
template <int CI, bool RELUIN>
__global__ void __launch_bounds__(256)
k_tconv(const float* __restrict__ x, const float* __restrict__ wT,
        const float* __restrict__ b, float* __restrict__ out) {
    __shared__ float xs[4 * CI * 16];  // 16-float rows: [pad, t0..t11, pad, pad, pad]
    const int tid = threadIdx.x;
    const int nl = tid >> 6;
    const int o = tid & 63;
    const int n0 = blockIdx.x * 4;

    for (int idx = tid; idx < 4 * CI * 12; idx += 256) {
        int nn = idx / (CI * 12);
        int r = idx - nn * CI * 12;
        int c = r / 12;
        int t = r - c * 12;
        float v = x[(n0 + nn) * (CI * 12) + r];
        if (RELUIN) v = fmaxf(v, 0.0f);
        xs[(nn * CI + c) * 16 + t + 1] = v;
    }
    for (int idx = tid; idx < 4 * CI; idx += 256) {
        int base = idx * 16;
        xs[base] = 0.0f;
        xs[base + 13] = 0.0f;
        xs[base + 14] = 0.0f;
        xs[base + 15] = 0.0f;
    }
    __syncthreads();

    float accP[12], accQ[12];
#pragma unroll
    for (int t = 0; t < 12; t++) { accP[t] = 0.0f; accQ[t] = 0.0f; }

    const float4* xsv = reinterpret_cast<const float4*>(xs) + nl * CI * 4;
    const float* wp = wT + o;

#pragma unroll 4
    for (int c = 0; c < CI; c++) {
        float4 a0 = xsv[0], a1 = xsv[1], a2 = xsv[2], a3 = xsv[3];
        xsv += 4;
        float xr[16];
        xr[0] = a0.x;  xr[1] = a0.y;  xr[2] = a0.z;  xr[3] = a0.w;
        xr[4] = a1.x;  xr[5] = a1.y;  xr[6] = a1.z;  xr[7] = a1.w;
        xr[8] = a2.x;  xr[9] = a2.y;  xr[10] = a2.z; xr[11] = a2.w;
        xr[12] = a3.x; xr[13] = a3.y; xr[14] = a3.z; xr[15] = a3.w;
        float w0 = wp[0],  w1 = wp[128], w2 = wp[256];
        float v0 = wp[64], v1 = wp[192], v2 = wp[320];
        wp += 384;
#pragma unroll
        for (int t = 0; t < 12; t++) {
            accP[t] += w0 * xr[t] + w1 * xr[t + 1] + w2 * xr[t + 2];
            accQ[t] += v0 * xr[t] + v1 * xr[t + 1] + v2 * xr[t + 2];
        }
    }

    float bp = b[o], bq = b[64 + o];
    float r[12];
#pragma unroll
    for (int t = 0; t < 12; t++) {
        float p = accP[t] + bp;
        float q = accQ[t] + bq;
        r[t] = p * (1.0f / (1.0f + __expf(-q)));
    }
    float4* op = reinterpret_cast<float4*>(out + ((n0 + nl) * 64 + o) * 12);
    op[0] = make_float4(r[0], r[1], r[2], r[3]);
    op[1] = make_float4(r[4], r[5], r[6], r[7]);
    op[2] = make_float4(r[8], r[9], r[10], r[11]);
}

// ---------------- channel mix (einsum nct,oc->not) ----------------
__global__ void __launch_bounds__(256)
k_mix(const float* __restrict__ x, const float* __restrict__ wT, float* __restrict__ out) {
    __shared__ float xs[4 * H * 12];
    const int tid = threadIdx.x;
    const int nl = tid >> 6;
    const int o = tid & 63;
    const int n0 = blockIdx.x * 4;

    for (int idx = tid; idx < 4 * H * 12; idx += 256)
        xs[idx] = x[n0 * H * 12 + idx];
    __syncthreads();

    float acc[12];
#pragma unroll
    for (int t = 0; t < 12; t++) acc[t] = 0.0f;

    const float4* xsv = reinterpret_cast<const float4*>(xs) + nl * H * 3;
    const float* wp = wT + o;
#pragma unroll 4
    for (int c = 0; c < H; c++) {
        float4 a0 = xsv[0], a1 = xsv[1], a2 = xsv[2];
        xsv += 3;
        float w = wp[0];
        wp += 64;
        acc[0] += w * a0.x;  acc[1] += w * a0.y;  acc[2] += w * a0.z;  acc[3] += w * a0.w;
        acc[4] += w * a1.x;  acc[5] += w * a1.y;  acc[6] += w * a1.z;  acc[7] += w * a1.w;
        acc[8] += w * a2.x;  acc[9] += w * a2.y;  acc[10] += w * a2.z; acc[11] += w * a2.w;
    }
    float4* op = reinterpret_cast<float4*>(out + ((n0 + nl) * 64 + o) * 12);
    op[0] = make_float4(acc[0], acc[1], acc[2], acc[3]);
    op[1] = make_float4(acc[4], acc[5], acc[6], acc[7]);
    op[2] = make_float4(acc[8], acc[9], acc[10], acc[11]);
}

// ---------------- GCN init: self-loop term + bias ----------------
// C[n,o,t] = B[n,o,t] * dis[n]^2 + b[o]
__global__ void k_gcn_init(const float* __restrict__ x, const float* __restrict__ b,
                           float* __restrict__ out) {
    int i = blockIdx.x * blockDim.x + threadIdx.x;  // float4 index
    if (i >= NNODES * 192) return;
    int n = i / 192;
    int j = i - n * 192;
    int o = j / 3;  // 3 float4 per (n,o) row
    float sn = g_dis[n];
    sn *= sn;
    float4 v = reinterpret_cast<const float4*>(x)[i];
    float bb = b[o];
    reinterpret_cast<float4*>(out)[i] =
        make_float4(v.x * sn + bb, v.y * sn + bb, v.z * sn + bb, v.w * sn + bb);
}

// ---------------- GCN edge scatter (warp per edge, vec4 reductions) ----------------
__global__ void __launch_bounds__(256)
k_scatter(const float* __restrict__ x, float* __restrict__ out,
          const int* __restrict__ src, const int* __restrict__ dst,
          const float* __restrict__ ew) {
    int w = (blockIdx.x * blockDim.x + threadIdx.x) >> 5;
    int lane = threadIdx.x & 31;
    if (w >= NEDGES) return;
    int s = src[w], d = dst[w];
    float coef = g_dis[s] * ew[w] * g_dis[d];
    const float4* xp = reinterpret_cast<const float4*>(x) + s * 192;
    float4* op = reinterpret_cast<float4*>(out) + d * 192;
#pragma unroll
    for (int i = 0; i < 6; i++) {
        float4 v = xp[lane + i * 32];
        float4* p = op + lane + i * 32;
        asm volatile("red.global.add.v4.f32 [%0], {%1, %2, %3, %4};"
                     :: "l"(p), "f"(v.x * coef), "f"(v.y * coef),
                        "f"(v.z * coef), "f"(v.w * coef)
                     : "memory");
    }
}

// ---------------- final conv (valid, output length 1) ----------------
__global__ void __launch_bounds__(64)
k_fin(const float* __restrict__ x, const float* __restrict__ w,
      const float* __restrict__ b, float* __restrict__ out) {
    __shared__ float xs[4 * FEAT];
    const int tid = threadIdx.x;  // 64
    const int n0 = blockIdx.x * 4;
    for (int idx = tid; idx < 4 * FEAT; idx += 64) xs[idx] = x[n0 * FEAT + idx];
    __syncthreads();
    int nl = tid >> 4;
    int oc = tid & 15;
    if (oc < 12) {
        const float4* xv = reinterpret_cast<const float4*>(xs) + nl * 192;
        const float4* wv = reinterpret_cast<const float4*>(w) + oc * 192;
        float acc = b[oc];
#pragma unroll 8
        for (int i = 0; i < 192; i++) {
            float4 a = xv[i], ww = wv[i];
            acc += a.x * ww.x + a.y * ww.y + a.z * ww.z + a.w * ww.w;
        }
        out[(n0 + nl) * 12 + oc] = acc;
    }
}

// ---------------- launch ----------------
extern "C" void kernel_launch(void* const* d_in, const int* in_sizes, int n_in,
                              void* d_out, int out_size) {
    const float* x      = (const float*)d_in[0];
    const int*   ei     = (const int*)d_in[1];
    const int*   src    = ei;
    const int*   dst    = ei + NEDGES;
    const float* ew     = (const float*)d_in[2];
    const float* tc1a_w = (const float*)d_in[3];
    const float* tc1a_b = (const float*)d_in[4];
    const float* gc1_w  = (const float*)d_in[5];
    const float* gc1_b  = (const float*)d_in[6];
    const float* tc1b_w = (const float*)d_in[7];
    const float* tc1b_b = (const float*)d_in[8];
    const float* tc2a_w = (const float*)d_in[9];
    const float* tc2a_b = (const float*)d_in[10];
    const float* gc2_w  = (const float*)d_in[11];
    const float* gc2_b  = (const float*)d_in[12];
    const float* tc2b_w = (const float*)d_in[13];
    const float* tc2b_b = (const float*)d_in[14];
    const float* fin_w  = (const float*)d_in[15];
    const float* fin_b  = (const float*)d_in[16];
    float* out = (float*)d_out;

    float *bA, *bB, *bC, *w1a, *w1b, *w2a, *w2b, *g1, *g2;
    cudaGetSymbolAddress((void**)&bA, g_bufA);
    cudaGetSymbolAddress((void**)&bB, g_bufB);
    cudaGetSymbolAddress((void**)&bC, g_bufC);
    cudaGetSymbolAddress((void**)&w1a, g_wt1a);
    cudaGetSymbolAddress((void**)&w1b, g_wt1b);
    cudaGetSymbolAddress((void**)&w2a, g_wt2a);
    cudaGetSymbolAddress((void**)&w2b, g_wt2b);
    cudaGetSymbolAddress((void**)&g1, g_gc1T);
    cudaGetSymbolAddress((void**)&g2, g_gc2T);

    // weight layout prep
    k_tw<<<(2 * H * CINCH * KW + 255) / 256, 256>>>(tc1a_w, w1a, CINCH);
    k_tw<<<(2 * H * H * KW + 255) / 256, 256>>>(tc1b_w, w1b, H);
    k_tw<<<(2 * H * H * KW + 255) / 256, 256>>>(tc2a_w, w2a, H);
    k_tw<<<(2 * H * H * KW + 255) / 256, 256>>>(tc2b_w, w2b, H);
    k_gw<<<(H * H + 255) / 256, 256>>>(gc1_w, g1);
    k_gw<<<(H * H + 255) / 256, 256>>>(gc2_w, g2);

    // degree normalization
    k_deg_init<<<(NNODES + 255) / 256, 256>>>();
    k_deg_acc<<<(NEDGES + 255) / 256, 256>>>(dst, ew);
    k_deg_fin<<<(NNODES + 255) / 256, 256>>>();

    const int NB = NNODES / 4;  // 2500

    // layer 1
    k_tconv<CINCH, false><<<NB, 256>>>(x, w1a, tc1a_b, bA);
    k_mix<<<NB, 256>>>(bA, g1, bB);
    k_gcn_init<<<(NNODES * 192 + 255) / 256, 256>>>(bB, gc1_b, bC);
    k_scatter<<<(NEDGES * 32 + 255) / 256, 256>>>(bB, bC, src, dst, ew);
    k_tconv<H, true><<<NB, 256>>>(bC, w1b, tc1b_b, bA);  // fused relu on load

    // layer 2
    k_tconv<H, false><<<NB, 256>>>(bA, w2a, tc2a_b, bB);
    k_mix<<<NB, 256>>>(bB, g2, bC);
    k_gcn_init<<<(NNODES * 192 + 255) / 256, 256>>>(bC, gc2_b, bA);
    k_scatter<<<(NEDGES * 32 + 255) / 256, 256>>>(bC, bA, src, dst, ew);
    k_tconv<H, true><<<NB, 256>>>(bA, w2b, tc2b_b, bB);  // fused relu on load

    // output head
    k_fin<<<NB, 64>>>(bB, fin_w, fin_b, out);
}

// round 3
// speedup vs baseline: 1.1359x; 1.1359x over previous
#include <cuda_runtime.h>

#define NNODES 10000
#define NEDGES 160000
#define CINCH  32
#define H      64
#define T      12
#define OUTC   12
#define KW     3
#define FEAT   (H * T)  // 768

typedef unsigned long long ull;

// ---------------- device scratch (no allocations allowed) ----------------
__device__ float g_bufA[NNODES * FEAT];
__device__ float g_bufB[NNODES * FEAT];
__device__ float g_bufC[NNODES * FEAT];
__device__ float g_dis[NNODES];              // deg accumulator, then rsqrt(deg)
__device__ ull   g_wt1a[2 * H * CINCH * KW]; // dup-packed {w,w}, layout [(c*K+k)*128 + o]
__device__ ull   g_wt1b[2 * H * H * KW];
__device__ ull   g_wt2a[2 * H * H * KW];
__device__ ull   g_wt2b[2 * H * H * KW];
__device__ ull   g_gc1T[H * H];              // dup-packed [c*64 + o]
__device__ ull   g_gc2T[H * H];
// CSR
__device__ int   g_cnt[NNODES];
__device__ int   g_fill[NNODES];
__device__ int   g_row[NNODES + 1];
__device__ int   g_col[NEDGES];
__device__ float g_nrm[NEDGES];

// ---------------- f32x2 helpers ----------------
#define FMA2(a, x, y) asm("fma.rn.f32x2 %0, %1, %2, %0;" : "+l"(a) : "l"(x), "l"(y))
__device__ __forceinline__ float lof(ull v) { return __uint_as_float((unsigned)(v & 0xffffffffull)); }
__device__ __forceinline__ float hif(ull v) { return __uint_as_float((unsigned)(v >> 32)); }
__device__ __forceinline__ ull dup2(float f) {
    unsigned u = __float_as_uint(f);
    return ((ull)u << 32) | (ull)u;
}

// ---------------- weight prep ----------------
// w[o][c][k]  ->  wT[(c*K+k)*128 + o] = {w,w}
__global__ void k_tw(const float* __restrict__ w, ull* __restrict__ wT, int cin) {
    int idx = blockIdx.x * blockDim.x + threadIdx.x;
    int tot = 2 * H * cin * KW;
    if (idx >= tot) return;
    int o = idx / (cin * KW);
    int r = idx - o * cin * KW;
    int c = r / KW;
    int k = r - c * KW;
    wT[(c * KW + k) * (2 * H) + o] = dup2(w[idx]);
}

// w[o][c] -> wT[c*64 + o] = {w,w}
__global__ void k_gw(const float* __restrict__ w, ull* __restrict__ wT) {
    int idx = blockIdx.x * blockDim.x + threadIdx.x;
    if (idx >= H * H) return;
    int o = idx / H, c = idx - o * H;
    wT[c * H + o] = dup2(w[idx]);
}

// ---------------- degree / histogram ----------------
__global__ void k_deg_init() {
    int n = blockIdx.x * blockDim.x + threadIdx.x;
    if (n < NNODES) { g_dis[n] = 1.0f; g_cnt[n] = 0; }
}
__global__ void k_deg_acc(const int* __restrict__ dst, const float* __restrict__ ew) {
    int e = blockIdx.x * blockDim.x + threadIdx.x;
    if (e < NEDGES) {
        int d = dst[e];
        atomicAdd(&g_dis[d], ew[e]);
        atomicAdd(&g_cnt[d], 1);
    }
}
__global__ void k_deg_fin() {
    int n = blockIdx.x * blockDim.x + threadIdx.x;
    if (n < NNODES) g_dis[n] = rsqrtf(g_dis[n]);  // deg >= 1 always (self loop)
}

// ---------------- exclusive scan (single block) ----------------
__global__ void k_scan() {
    __shared__ int sh[1024];
    __shared__ int carry;
    int tid = threadIdx.x;
    if (tid == 0) carry = 0;
    __syncthreads();
    for (int base = 0; base < NNODES; base += 1024) {
        int i = base + tid;
        int v = (i < NNODES) ? g_cnt[i] : 0;
        sh[tid] = v;
        __syncthreads();
        for (int off = 1; off < 1024; off <<= 1) {
            int t = (tid >= off) ? sh[tid - off] : 0;
            __syncthreads();
            sh[tid] += t;
            __syncthreads();
        }
        if (i < NNODES) {
            g_row[i] = carry + sh[tid] - v;
            g_fill[i] = 0;
        }
        __syncthreads();
        if (tid == 1023) carry += sh[1023];
        __syncthreads();
    }
    if (tid == 0) g_row[NNODES] = carry;
}

__global__ void k_fill(const int* __restrict__ src, const int* __restrict__ dst,
                       const float* __restrict__ ew) {
    int e = blockIdx.x * blockDim.x + threadIdx.x;
    if (e >= NEDGES) return;
    int s = src[e], d = dst[e];
    int pos = g_row[d] + atomicAdd(&g_fill[d], 1);
    g_col[pos] = s;
    g_nrm[pos] = g_dis[s] * ew[e] * g_dis[d];
}

// ---------------- gated temporal conv (f32x2 packed over time pairs) ----------------
// block: 256 threads = 4 nodes x 64 output channels.
// shared row per (n,c): 32 floats = xp[16] (pad + x0..x11 + 3 pad) then xq[16] (x0..x11 + 4 pad)
template <int CI, bool RELUIN>
__global__ void __launch_bounds__(256)
k_tconv(const float* __restrict__ x, const ull* __restrict__ wT,
        const float* __restrict__ b, float* __restrict__ out) {
    __shared__ __align__(16) float xs[4 * CI * 32];
    const int tid = threadIdx.x;
    const int nl = tid >> 6;
    const int o = tid & 63;
    const int n0 = blockIdx.x * 4;

    for (int idx = tid; idx < 4 * CI * 12; idx += 256) {
        int nn = idx / (CI * 12);
        int r = idx - nn * (CI * 12);
        int c = r / 12;
        int t = r - c * 12;
        float v = x[(n0 + nn) * (CI * 12) + r];
        if (RELUIN) v = fmaxf(v, 0.0f);
        float* row = xs + (nn * CI + c) * 32;
        row[t + 1] = v;   // xp
        row[16 + t] = v;  // xq (shifted view)
    }
    for (int idx = tid; idx < 4 * CI; idx += 256) {
        float* row = xs + idx * 32;
        row[0] = 0.f; row[13] = 0.f; row[14] = 0.f; row[15] = 0.f;
        row[28] = 0.f; row[29] = 0.f; row[30] = 0.f; row[31] = 0.f;
    }
    __syncthreads();

    ull P[6], Q[6];
#pragma unroll
    for (int i = 0; i < 6; i++) { P[i] = 0ull; Q[i] = 0ull; }

    const ulonglong2* ep = reinterpret_cast<const ulonglong2*>(xs) + nl * CI * 8;
    const ull* wp = wT + o;

#pragma unroll 2
    for (int c = 0; c < CI; c++) {
        ulonglong2 a0 = ep[0], a1 = ep[1], a2 = ep[2], a3 = ep[3];
        ulonglong2 b0 = ep[4], b1 = ep[5], b2 = ep[6];
        ep += 8;
        ull E[8] = {a0.x, a0.y, a1.x, a1.y, a2.x, a2.y, a3.x, a3.y};
        ull O[6] = {b0.x, b0.y, b1.x, b1.y, b2.x, b2.y};
        ull w0 = wp[0],  w1 = wp[128], w2 = wp[256];
        ull v0 = wp[64], v1 = wp[192], v2 = wp[320];
        wp += 384;
#pragma unroll
        for (int i = 0; i < 6; i++) {
            FMA2(P[i], w0, E[i]);
            FMA2(P[i], w1, O[i]);
            FMA2(P[i], w2, E[i + 1]);
            FMA2(Q[i], v0, E[i]);
            FMA2(Q[i], v1, O[i]);
            FMA2(Q[i], v2, E[i + 1]);
        }
    }

    float bp = b[o], bq = b[64 + o];
    float r[12];
#pragma unroll
    for (int i = 0; i < 6; i++) {
        float p0 = lof(P[i]) + bp, p1 = hif(P[i]) + bp;
        float q0 = lof(Q[i]) + bq, q1 = hif(Q[i]) + bq;
        r[2 * i]     = p0 * (1.0f / (1.0f + __expf(-q0)));
        r[2 * i + 1] = p1 * (1.0f / (1.0f + __expf(-q1)));
    }
    float4* op = reinterpret_cast<float4*>(out + ((n0 + nl) * 64 + o) * 12);
    op[0] = make_float4(r[0], r[1], r[2], r[3]);
    op[1] = make_float4(r[4], r[5], r[6], r[7]);
    op[2] = make_float4(r[8], r[9], r[10], r[11]);
}

// ---------------- channel mix (einsum nct,oc->not), f32x2 packed ----------------
__global__ void __launch_bounds__(256)
k_mix(const float* __restrict__ x, const ull* __restrict__ wT, float* __restrict__ out) {
    __shared__ __align__(16) float xs[4 * H * 16];
    const int tid = threadIdx.x;
    const int nl = tid >> 6;
    const int o = tid & 63;
    const int n0 = blockIdx.x * 4;

    for (int idx = tid; idx < 4 * H * 12; idx += 256) {
        int nn = idx / (H * 12);
        int r = idx - nn * (H * 12);
        int c = r / 12;
        int t = r - c * 12;
        xs[(nn * H + c) * 16 + t] = x[n0 * (H * 12) + idx];
    }
    __syncthreads();

    ull M[6];
#pragma unroll
    for (int i = 0; i < 6; i++) M[i] = 0ull;

    const ulonglong2* ep = reinterpret_cast<const ulonglong2*>(xs) + nl * H * 4;
    const ull* wp = wT + o;
#pragma unroll 4
    for (int c = 0; c < H; c++) {
        ulonglong2 a0 = ep[0], a1 = ep[1], a2 = ep[2];
        ep += 4;
        ull w = wp[0];
        wp += 64;
        FMA2(M[0], w, a0.x); FMA2(M[1], w, a0.y);
        FMA2(M[2], w, a1.x); FMA2(M[3], w, a1.y);
        FMA2(M[4], w, a2.x); FMA2(M[5], w, a2.y);
    }
    float4* op = reinterpret_cast<float4*>(out + ((n0 + nl) * 64 + o) * 12);
    op[0] = make_float4(lof(M[0]), hif(M[0]), lof(M[1]), hif(M[1]));
    op[1] = make_float4(lof(M[2]), hif(M[2]), lof(M[3]), hif(M[3]));
    op[2] = make_float4(lof(M[4]), hif(M[4]), lof(M[5]), hif(M[5]));
}

// ---------------- GCN gather: out[n] = relu(b + dis[n]^2 * x[n] + sum_e nrm*x[src]) ----------------
__global__ void __launch_bounds__(192)
k_gather(const float* __restrict__ x, float* __restrict__ out, const float* __restrict__ b) {
    const int n = blockIdx.x;
    const int j = threadIdx.x;  // 0..191 float4 slots
    float bb = b[j / 3];
    float ds = g_dis[n];
    float sc = ds * ds;
    const float4* xv = reinterpret_cast<const float4*>(x);
    float4 v = xv[n * 192 + j];
    float4 acc = make_float4(bb + sc * v.x, bb + sc * v.y, bb + sc * v.z, bb + sc * v.w);
    int e = g_row[n];
    const int end = g_row[n + 1];
    for (; e < end; e++) {
        int s = __ldg(&g_col[e]);
        float c = __ldg(&g_nrm[e]);
        float4 u = xv[s * 192 + j];
        acc.x += c * u.x; acc.y += c * u.y;
        acc.z += c * u.z; acc.w += c * u.w;
    }
    reinterpret_cast<float4*>(out)[n * 192 + j] =
        make_float4(fmaxf(acc.x, 0.f), fmaxf(acc.y, 0.f), fmaxf(acc.z, 0.f), fmaxf(acc.w, 0.f));
}

// ---------------- final conv (valid, output length 1) ----------------
__global__ void __launch_bounds__(64)
k_fin(const float* __restrict__ x, const float* __restrict__ w,
      const float* __restrict__ b, float* __restrict__ out) {
    __shared__ __align__(16) float xs[4 * FEAT];
    const int tid = threadIdx.x;
    const int n0 = blockIdx.x * 4;
    for (int idx = tid; idx < 4 * FEAT; idx += 64) xs[idx] = x[n0 * FEAT + idx];
    __syncthreads();
    int nl = tid >> 4;
    int oc = tid & 15;
    if (oc < 12) {
        const float4* xv = reinterpret_cast<const float4*>(xs) + nl * 192;
        const float4* wv = reinterpret_cast<const float4*>(w) + oc * 192;
        float acc = b[oc];
#pragma unroll 8
        for (int i = 0; i < 192; i++) {
            float4 a = xv[i], ww = wv[i];
            acc += a.x * ww.x + a.y * ww.y + a.z * ww.z + a.w * ww.w;
        }
        out[(n0 + nl) * 12 + oc] = acc;
    }
}

// ---------------- launch ----------------
extern "C" void kernel_launch(void* const* d_in, const int* in_sizes, int n_in,
                              void* d_out, int out_size) {
    const float* x      = (const float*)d_in[0];
    const int*   ei     = (const int*)d_in[1];
    const int*   src    = ei;
    const int*   dst    = ei + NEDGES;
    const float* ew     = (const float*)d_in[2];
    const float* tc1a_w = (const float*)d_in[3];
    const float* tc1a_b = (const float*)d_in[4];
    const float* gc1_w  = (const float*)d_in[5];
    const float* gc1_b  = (const float*)d_in[6];
    const float* tc1b_w = (const float*)d_in[7];
    const float* tc1b_b = (const float*)d_in[8];
    const float* tc2a_w = (const float*)d_in[9];
    const float* tc2a_b = (const float*)d_in[10];
    const float* gc2_w  = (const float*)d_in[11];
    const float* gc2_b  = (const float*)d_in[12];
    const float* tc2b_w = (const float*)d_in[13];
    const float* tc2b_b = (const float*)d_in[14];
    const float* fin_w  = (const float*)d_in[15];
    const float* fin_b  = (const float*)d_in[16];
    float* out = (float*)d_out;

    float *bA, *bB, *bC;
    ull *w1a, *w1b, *w2a, *w2b, *g1, *g2;
    cudaGetSymbolAddress((void**)&bA, g_bufA);
    cudaGetSymbolAddress((void**)&bB, g_bufB);
    cudaGetSymbolAddress((void**)&bC, g_bufC);
    cudaGetSymbolAddress((void**)&w1a, g_wt1a);
    cudaGetSymbolAddress((void**)&w1b, g_wt1b);
    cudaGetSymbolAddress((void**)&w2a, g_wt2a);
    cudaGetSymbolAddress((void**)&w2b, g_wt2b);
    cudaGetSymbolAddress((void**)&g1, g_gc1T);
    cudaGetSymbolAddress((void**)&g2, g_gc2T);

    // weight layout prep (dup-packed for f32x2)
    k_tw<<<(2 * H * CINCH * KW + 255) / 256, 256>>>(tc1a_w, w1a, CINCH);
    k_tw<<<(2 * H * H * KW + 255) / 256, 256>>>(tc1b_w, w1b, H);
    k_tw<<<(2 * H * H * KW + 255) / 256, 256>>>(tc2a_w, w2a, H);
    k_tw<<<(2 * H * H * KW + 255) / 256, 256>>>(tc2b_w, w2b, H);
    k_gw<<<(H * H + 255) / 256, 256>>>(gc1_w, g1);
    k_gw<<<(H * H + 255) / 256, 256>>>(gc2_w, g2);

    // degree normalization + CSR build
    k_deg_init<<<(NNODES + 255) / 256, 256>>>();
    k_deg_acc<<<(NEDGES + 255) / 256, 256>>>(dst, ew);
    k_deg_fin<<<(NNODES + 255) / 256, 256>>>();
    k_scan<<<1, 1024>>>();
    k_fill<<<(NEDGES + 255) / 256, 256>>>(src, dst, ew);

    const int NB = NNODES / 4;  // 2500

    // layer 1
    k_tconv<CINCH, false><<<NB, 256>>>(x, w1a, tc1a_b, bA);
    k_mix<<<NB, 256>>>(bA, g1, bB);
    k_gather<<<NNODES, 192>>>(bB, bC, gc1_b);            // bias+selfloop+relu fused
    k_tconv<H, false><<<NB, 256>>>(bC, w1b, tc1b_b, bA); // relu already applied

    // layer 2
    k_tconv<H, false><<<NB, 256>>>(bA, w2a, tc2a_b, bB);
    k_mix<<<NB, 256>>>(bB, g2, bC);
    k_gather<<<NNODES, 192>>>(bC, bA, gc2_b);
    k_tconv<H, false><<<NB, 256>>>(bA, w2b, tc2b_b, bB);

    // output head
    k_fin<<<NB, 64>>>(bB, fin_w, fin_b, out);
}

// round 4
// speedup vs baseline: 1.1970x; 1.0538x over previous
#include <cuda_runtime.h>

#define NNODES 10000
#define NEDGES 160000
#define CINCH  32
#define H      64
#define T      12
#define OUTC   12
#define KW     3
#define FEAT   (H * T)  // 768

typedef unsigned long long ull;

// ---------------- device scratch (no allocations allowed) ----------------
__device__ float g_bufA[NNODES * FEAT];
__device__ float g_bufB[NNODES * FEAT];
__device__ float g_bufC[NNODES * FEAT];
__device__ float g_dis[NNODES];               // deg accumulator, then rsqrt(deg)
// tconv weights: [c][o(128)][k pad to 4] plain float (pad stays 0 via zero-init)
__device__ float g_wt1a[CINCH * 2 * H * 4];
__device__ float g_wt1b[H * 2 * H * 4];
__device__ float g_wt2a[H * 2 * H * 4];
__device__ float g_wt2b[H * 2 * H * 4];
__device__ ull   g_gc1T[H * H];               // dup-packed [c*64 + o]
__device__ ull   g_gc2T[H * H];
// CSR
__device__ int   g_cnt[NNODES];
__device__ int   g_fill[NNODES];
__device__ int   g_row[NNODES + 1];
__device__ int   g_col[NEDGES];
__device__ float g_nrm[NEDGES];

// ---------------- f32x2 helpers ----------------
#define FMA2(a, x, y) asm("fma.rn.f32x2 %0, %1, %2, %0;" : "+l"(a) : "l"(x), "l"(y))
__device__ __forceinline__ float lof(ull v) { return __uint_as_float((unsigned)(v & 0xffffffffull)); }
__device__ __forceinline__ float hif(ull v) { return __uint_as_float((unsigned)(v >> 32)); }
__device__ __forceinline__ ull dupr(float f) {
    ull r;
    asm("mov.b64 %0, {%1, %1};" : "=l"(r) : "f"(f));
    return r;
}
__device__ __forceinline__ ull dup2h(float f) {  // host-side style dup for prep kernels
    unsigned u = __float_as_uint(f);
    return ((ull)u << 32) | (ull)u;
}

// ---------------- weight prep ----------------
// w[o][c][k] -> wT[(c*128 + o)*4 + k]   (k<3; pad k=3 remains 0)
__global__ void k_tw(const float* __restrict__ w, float* __restrict__ wT, int cin) {
    int idx = blockIdx.x * blockDim.x + threadIdx.x;
    int tot = 2 * H * cin * KW;
    if (idx >= tot) return;
    int o = idx / (cin * KW);
    int r = idx - o * cin * KW;
    int c = r / KW;
    int k = r - c * KW;
    wT[(c * 128 + o) * 4 + k] = w[idx];
}

// w[o][c] -> wT[c*64 + o] = {w,w}
__global__ void k_gw(const float* __restrict__ w, ull* __restrict__ wT) {
    int idx = blockIdx.x * blockDim.x + threadIdx.x;
    if (idx >= H * H) return;
    int o = idx / H, c = idx - o * H;
    wT[c * H + o] = dup2h(w[idx]);
}

// ---------------- degree / histogram ----------------
__global__ void k_deg_init() {
    int n = blockIdx.x * blockDim.x + threadIdx.x;
    if (n < NNODES) { g_dis[n] = 1.0f; g_cnt[n] = 0; }
}
__global__ void k_deg_acc(const int* __restrict__ dst, const float* __restrict__ ew) {
    int e = blockIdx.x * blockDim.x + threadIdx.x;
    if (e < NEDGES) {
        int d = dst[e];
        atomicAdd(&g_dis[d], ew[e]);
        atomicAdd(&g_cnt[d], 1);
    }
}
__global__ void k_deg_fin() {
    int n = blockIdx.x * blockDim.x + threadIdx.x;
    if (n < NNODES) g_dis[n] = rsqrtf(g_dis[n]);  // deg >= 1 always (self loop)
}

// ---------------- exclusive scan (single block) ----------------
__global__ void k_scan() {
    __shared__ int sh[1024];
    __shared__ int carry;
    int tid = threadIdx.x;
    if (tid == 0) carry = 0;
    __syncthreads();
    for (int base = 0; base < NNODES; base += 1024) {
        int i = base + tid;
        int v = (i < NNODES) ? g_cnt[i] : 0;
        sh[tid] = v;
        __syncthreads();
        for (int off = 1; off < 1024; off <<= 1) {
            int t = (tid >= off) ? sh[tid - off] : 0;
            __syncthreads();
            sh[tid] += t;
            __syncthreads();
        }
        if (i < NNODES) {
            g_row[i] = carry + sh[tid] - v;
            g_fill[i] = 0;
        }
        __syncthreads();
        if (tid == 1023) carry += sh[1023];
        __syncthreads();
    }
    if (tid == 0) g_row[NNODES] = carry;
}

__global__ void k_fill(const int* __restrict__ src, const int* __restrict__ dst,
                       const float* __restrict__ ew) {
    int e = blockIdx.x * blockDim.x + threadIdx.x;
    if (e >= NEDGES) return;
    int s = src[e], d = dst[e];
    int pos = g_row[d] + atomicAdd(&g_fill[d], 1);
    g_col[pos] = s;
    g_nrm[pos] = g_dis[s] * ew[e] * g_dis[d];
}

// ---------------- tconv core: load x to smem, run gated conv, return r[12] ----------------
// block: 256 threads = 4 nodes x 64 output channels.
// xs row per (n,c): 32 floats = xp[16](pad+x0..11+3pad) then xq[16](x0..11+4pad)
template <int CI>
__device__ __forceinline__ void tconv_core(const float* __restrict__ x,
                                           const float* __restrict__ wT,
                                           const float* __restrict__ b,
                                           float* xs, int tid, int nl, int o, int n0,
                                           float (&r)[12]) {
    for (int idx = tid; idx < 4 * CI * 12; idx += 256) {
        int nn = idx / (CI * 12);
        int rr = idx - nn * (CI * 12);
        int c = rr / 12;
        int t = rr - c * 12;
        float v = x[(n0 + nn) * (CI * 12) + rr];
        float* row = xs + (nn * CI + c) * 32;
        row[t + 1] = v;
        row[16 + t] = v;
    }
    for (int idx = tid; idx < 4 * CI; idx += 256) {
        float* row = xs + idx * 32;
        row[0] = 0.f; row[13] = 0.f; row[14] = 0.f; row[15] = 0.f;
        row[28] = 0.f; row[29] = 0.f; row[30] = 0.f; row[31] = 0.f;
    }
    __syncthreads();

    ull P[6], Q[6];
#pragma unroll
    for (int i = 0; i < 6; i++) { P[i] = 0ull; Q[i] = 0ull; }

    const ulonglong2* ep = reinterpret_cast<const ulonglong2*>(xs) + nl * CI * 8;
    const float4* wv = reinterpret_cast<const float4*>(wT) + o;

#pragma unroll 2
    for (int c = 0; c < CI; c++) {
        ulonglong2 a0 = ep[0], a1 = ep[1], a2 = ep[2], a3 = ep[3];
        ulonglong2 b0 = ep[4], b1 = ep[5], b2 = ep[6];
        ep += 8;
        ull E[8] = {a0.x, a0.y, a1.x, a1.y, a2.x, a2.y, a3.x, a3.y};
        ull O[6] = {b0.x, b0.y, b1.x, b1.y, b2.x, b2.y};
        float4 wp4 = wv[0];       // P taps for this (c,o)
        float4 wq4 = wv[64];      // Q taps
        wv += 128;
        ull w0 = dupr(wp4.x), w1 = dupr(wp4.y), w2 = dupr(wp4.z);
        ull v0 = dupr(wq4.x), v1 = dupr(wq4.y), v2 = dupr(wq4.z);
#pragma unroll
        for (int i = 0; i < 6; i++) {
            FMA2(P[i], w0, E[i]);
            FMA2(P[i], w1, O[i]);
            FMA2(P[i], w2, E[i + 1]);
            FMA2(Q[i], v0, E[i]);
            FMA2(Q[i], v1, O[i]);
            FMA2(Q[i], v2, E[i + 1]);
        }
    }

    float bp = b[o], bq = b[64 + o];
#pragma unroll
    for (int i = 0; i < 6; i++) {
        float p0 = lof(P[i]) + bp, p1 = hif(P[i]) + bp;
        float q0 = lof(Q[i]) + bq, q1 = hif(Q[i]) + bq;
        r[2 * i]     = p0 * (1.0f / (1.0f + __expf(-q0)));
        r[2 * i + 1] = p1 * (1.0f / (1.0f + __expf(-q1)));
    }
}

// ---------------- plain tconv (tconv1b) ----------------
template <int CI>
__global__ void __launch_bounds__(256)
k_tconv(const float* __restrict__ x, const float* __restrict__ wT,
        const float* __restrict__ b, float* __restrict__ out) {
    __shared__ __align__(16) float xs[4 * CI * 32];
    const int tid = threadIdx.x;
    const int nl = tid >> 6;
    const int o = tid & 63;
    const int n0 = blockIdx.x * 4;
    float r[12];
    tconv_core<CI>(x, wT, b, xs, tid, nl, o, n0, r);
    float4* op = reinterpret_cast<float4*>(out + ((n0 + nl) * 64 + o) * 12);
    op[0] = make_float4(r[0], r[1], r[2], r[3]);
    op[1] = make_float4(r[4], r[5], r[6], r[7]);
    op[2] = make_float4(r[8], r[9], r[10], r[11]);
}

// ---------------- tconv + channel mix fused ----------------
template <int CI>
__global__ void __launch_bounds__(256)
k_tconv_mix(const float* __restrict__ x, const float* __restrict__ wT,
            const float* __restrict__ b, const ull* __restrict__ gw,
            float* __restrict__ out) {
    __shared__ __align__(16) float xs[4 * CI * 32];
    __shared__ __align__(16) float sb[4 * 64 * 16];
    const int tid = threadIdx.x;
    const int nl = tid >> 6;
    const int o = tid & 63;
    const int n0 = blockIdx.x * 4;
    float r[12];
    tconv_core<CI>(x, wT, b, xs, tid, nl, o, n0, r);

    float4* srow = reinterpret_cast<float4*>(sb + (nl * 64 + o) * 16);
    srow[0] = make_float4(r[0], r[1], r[2], r[3]);
    srow[1] = make_float4(r[4], r[5], r[6], r[7]);
    srow[2] = make_float4(r[8], r[9], r[10], r[11]);
    __syncthreads();

    ull M[6];
#pragma unroll
    for (int i = 0; i < 6; i++) M[i] = 0ull;
    const ulonglong2* sp = reinterpret_cast<const ulonglong2*>(sb) + nl * 64 * 4;
    const ull* gp = gw + o;
#pragma unroll 4
    for (int c = 0; c < 64; c++) {
        ulonglong2 a0 = sp[0], a1 = sp[1], a2 = sp[2];
        sp += 4;
        ull w = gp[0];
        gp += 64;
        FMA2(M[0], w, a0.x); FMA2(M[1], w, a0.y);
        FMA2(M[2], w, a1.x); FMA2(M[3], w, a1.y);
        FMA2(M[4], w, a2.x); FMA2(M[5], w, a2.y);
    }
    float4* op = reinterpret_cast<float4*>(out + ((n0 + nl) * 64 + o) * 12);
    op[0] = make_float4(lof(M[0]), hif(M[0]), lof(M[1]), hif(M[1]));
    op[1] = make_float4(lof(M[2]), hif(M[2]), lof(M[3]), hif(M[3]));
    op[2] = make_float4(lof(M[4]), hif(M[4]), lof(M[5]), hif(M[5]));
}

// ---------------- tconv + final 1x12 conv fused ----------------
__global__ void __launch_bounds__(256)
k_tconv_fin(const float* __restrict__ x, const float* __restrict__ wT,
            const float* __restrict__ b, const float* __restrict__ fw,
            const float* __restrict__ fb, float* __restrict__ out) {
    __shared__ __align__(16) float xs[4 * H * 32];
    __shared__ __align__(16) float sb[4 * 64 * 16];
    const int tid = threadIdx.x;
    const int nl = tid >> 6;
    const int o = tid & 63;
    const int n0 = blockIdx.x * 4;
    float r[12];
    tconv_core<H>(x, wT, b, xs, tid, nl, o, n0, r);

    float4* srow = reinterpret_cast<float4*>(sb + (nl * 64 + o) * 16);
    srow[0] = make_float4(r[0], r[1], r[2], r[3]);
    srow[1] = make_float4(r[4], r[5], r[6], r[7]);
    srow[2] = make_float4(r[8], r[9], r[10], r[11]);
    __syncthreads();

    // fin: 4 threads per oc, split over channel quarters, shfl reduce.
    int sub = tid & 3;
    int oc = (tid >> 2) & 15;
    int ocr = oc < 12 ? oc : 11;  // clamp to keep reads in-bounds; lanes stay convergent
    float acc = 0.0f;
    const float4* wrow = reinterpret_cast<const float4*>(fw + ocr * FEAT + sub * 16 * 12);
#pragma unroll 4
    for (int c = 0; c < 16; c++) {
        const float4* sr = reinterpret_cast<const float4*>(sb + (nl * 64 + sub * 16 + c) * 16);
        float4 a0 = sr[0], a1 = sr[1], a2 = sr[2];
        float4 w0 = wrow[0], w1 = wrow[1], w2 = wrow[2];
        wrow += 3;
        acc += a0.x * w0.x + a0.y * w0.y + a0.z * w0.z + a0.w * w0.w;
        acc += a1.x * w1.x + a1.y * w1.y + a1.z * w1.z + a1.w * w1.w;
        acc += a2.x * w2.x + a2.y * w2.y + a2.z * w2.z + a2.w * w2.w;
    }
    acc += __shfl_xor_sync(0xffffffffu, acc, 1);
    acc += __shfl_xor_sync(0xffffffffu, acc, 2);
    if (sub == 0 && oc < 12)
        out[(n0 + nl) * 12 + oc] = acc + fb[oc];
}

// ---------------- GCN gather: out[n] = relu(b + dis[n]^2 * x[n] + sum_e nrm*x[src]) --------
__global__ void __launch_bounds__(192)
k_gather(const float* __restrict__ x, float* __restrict__ out, const float* __restrict__ b) {
    const int n = blockIdx.x;
    const int j = threadIdx.x;  // 0..191 float4 slots
    float bb = b[j / 3];
    float ds = g_dis[n];
    float sc = ds * ds;
    const float4* xv = reinterpret_cast<const float4*>(x);
    float4 v = xv[n * 192 + j];
    float4 acc = make_float4(bb + sc * v.x, bb + sc * v.y, bb + sc * v.z, bb + sc * v.w);
    int e = g_row[n];
    const int end = g_row[n + 1];
    for (; e < end; e++) {
        int s = __ldg(&g_col[e]);
        float c = __ldg(&g_nrm[e]);
        float4 u = xv[s * 192 + j];
        acc.x += c * u.x; acc.y += c * u.y;
        acc.z += c * u.z; acc.w += c * u.w;
    }
    reinterpret_cast<float4*>(out)[n * 192 + j] =
        make_float4(fmaxf(acc.x, 0.f), fmaxf(acc.y, 0.f), fmaxf(acc.z, 0.f), fmaxf(acc.w, 0.f));
}

// ---------------- launch ----------------
extern "C" void kernel_launch(void* const* d_in, const int* in_sizes, int n_in,
                              void* d_out, int out_size) {
    const float* x      = (const float*)d_in[0];
    const int*   ei     = (const int*)d_in[1];
    const int*   src    = ei;
    const int*   dst    = ei + NEDGES;
    const float* ew     = (const float*)d_in[2];
    const float* tc1a_w = (const float*)d_in[3];
    const float* tc1a_b = (const float*)d_in[4];
    const float* gc1_w  = (const float*)d_in[5];
    const float* gc1_b  = (const float*)d_in[6];
    const float* tc1b_w = (const float*)d_in[7];
    const float* tc1b_b = (const float*)d_in[8];
    const float* tc2a_w = (const float*)d_in[9];
    const float* tc2a_b = (const float*)d_in[10];
    const float* gc2_w  = (const float*)d_in[11];
    const float* gc2_b  = (const float*)d_in[12];
    const float* tc2b_w = (const float*)d_in[13];
    const float* tc2b_b = (const float*)d_in[14];
    const float* fin_w  = (const float*)d_in[15];
    const float* fin_b  = (const float*)d_in[16];
    float* out = (float*)d_out;

    float *bA, *bB, *bC, *w1a, *w1b, *w2a, *w2b;
    ull *g1, *g2;
    cudaGetSymbolAddress((void**)&bA, g_bufA);
    cudaGetSymbolAddress((void**)&bB, g_bufB);
    cudaGetSymbolAddress((void**)&bC, g_bufC);
    cudaGetSymbolAddress((void**)&w1a, g_wt1a);
    cudaGetSymbolAddress((void**)&w1b, g_wt1b);
    cudaGetSymbolAddress((void**)&w2a, g_wt2a);
    cudaGetSymbolAddress((void**)&w2b, g_wt2b);
    cudaGetSymbolAddress((void**)&g1, g_gc1T);
    cudaGetSymbolAddress((void**)&g2, g_gc2T);

    // weight layout prep
    k_tw<<<(2 * H * CINCH * KW + 255) / 256, 256>>>(tc1a_w, w1a, CINCH);
    k_tw<<<(2 * H * H * KW + 255) / 256, 256>>>(tc1b_w, w1b, H);
    k_tw<<<(2 * H * H * KW + 255) / 256, 256>>>(tc2a_w, w2a, H);
    k_tw<<<(2 * H * H * KW + 255) / 256, 256>>>(tc2b_w, w2b, H);
    k_gw<<<(H * H + 255) / 256, 256>>>(gc1_w, g1);
    k_gw<<<(H * H + 255) / 256, 256>>>(gc2_w, g2);

    // degree normalization + CSR build
    k_deg_init<<<(NNODES + 255) / 256, 256>>>();
    k_deg_acc<<<(NEDGES + 255) / 256, 256>>>(dst, ew);
    k_deg_fin<<<(NNODES + 255) / 256, 256>>>();
    k_scan<<<1, 1024>>>();
    k_fill<<<(NEDGES + 255) / 256, 256>>>(src, dst, ew);

    const int NB = NNODES / 4;  // 2500

    // layer 1
    k_tconv_mix<CINCH><<<NB, 256>>>(x, w1a, tc1a_b, g1, bA);   // tconv1a + mix1
    k_gather<<<NNODES, 192>>>(bA, bB, gc1_b);                   // +bias +selfloop +relu
    k_tconv<H><<<NB, 256>>>(bB, w1b, tc1b_b, bC);               // tconv1b

    // layer 2
    k_tconv_mix<H><<<NB, 256>>>(bC, w2a, tc2a_b, g2, bA);       // tconv2a + mix2
    k_gather<<<NNODES, 192>>>(bA, bB, gc2_b);
    k_tconv_fin<<<NB, 256>>>(bB, w2b, tc2b_b, fin_w, fin_b, out);  // tconv2b + fin
}